// round 15
// baseline (speedup 1.0000x reference)
#include <cuda_runtime.h>
#include <cuda_bf16.h>
#include <math.h>
#include <stdint.h>

#define D     64
#define TM    128       // x rows per CTA
#define KP    128       // all prototypes in every CTA
#define NTH   256
#define ROWB  384       // bytes per B row; chunk0=hi @0, chunk2=lo @+256

// smem layout
#define SM_B   0                      // 128 x 384B = 49152
#define SM_P2  49152                  // 128 floats
#define SM_DYN (SM_P2 + 512)          // 49664 B

static __device__ __forceinline__ uint32_t sw(uint32_t off) {
    return off ^ ((off >> 3) & 0x70);
}

static __device__ __forceinline__ uint32_t smem_u32(const void* p) {
    uint32_t a;
    asm("{ .reg .u64 t; cvta.to.shared.u64 t, %1; cvt.u32.u64 %0, t; }" : "=r"(a) : "l"(p));
    return a;
}

static __device__ __forceinline__ void ldsm_x4(uint32_t* r, uint32_t addr) {
    asm volatile("ldmatrix.sync.aligned.m8n8.x4.shared.b16 {%0,%1,%2,%3}, [%4];"
                 : "=r"(r[0]), "=r"(r[1]), "=r"(r[2]), "=r"(r[3]) : "r"(addr));
}

static __device__ __forceinline__ void mma_bf16(float* c, const uint32_t* a,
                                                uint32_t b0, uint32_t b1) {
    asm volatile(
        "mma.sync.aligned.m16n8k16.row.col.f32.bf16.bf16.f32 "
        "{%0,%1,%2,%3}, {%4,%5,%6,%7}, {%8,%9}, {%0,%1,%2,%3};"
        : "+f"(c[0]), "+f"(c[1]), "+f"(c[2]), "+f"(c[3])
        : "r"(a[0]), "r"(a[1]), "r"(a[2]), "r"(a[3]), "r"(b0), "r"(b1));
}

static __device__ __forceinline__ void split2(float v0, float v1,
                                              uint32_t& hi, uint32_t& lo) {
    __nv_bfloat162 h = __floats2bfloat162_rn(v0, v1);
    float r0 = v0 - __bfloat162float(__low2bfloat16(h));
    float r1 = v1 - __bfloat162float(__high2bfloat16(h));
    __nv_bfloat162 l = __floats2bfloat162_rn(r0, r1);
    hi = *reinterpret_cast<uint32_t*>(&h);
    lo = *reinterpret_cast<uint32_t*>(&l);
}

// ---- packed f32x2 helpers (sm_100-family PTX, no .a feature) ----
static __device__ __forceinline__ uint64_t pk(float a, float b) {
    uint64_t r;
    asm("mov.b64 %0, {%1, %2};" : "=l"(r) : "f"(a), "f"(b));
    return r;
}
static __device__ __forceinline__ void upk(uint64_t v, float& a, float& b) {
    asm("mov.b64 {%0, %1}, %2;" : "=f"(a), "=f"(b) : "l"(v));
}
static __device__ __forceinline__ uint64_t fma2(uint64_t a, uint64_t b, uint64_t c) {
    uint64_t r;
    asm("fma.rn.f32x2 %0, %1, %2, %3;" : "=l"(r) : "l"(a), "l"(b), "l"(c));
    return r;
}
static __device__ __forceinline__ uint64_t add2(uint64_t a, uint64_t b) {
    uint64_t r;
    asm("add.rn.f32x2 %0, %1, %2;" : "=l"(r) : "l"(a), "l"(b));
    return r;
}
static __device__ __forceinline__ uint64_t mul2(uint64_t a, uint64_t b) {
    uint64_t r;
    asm("mul.rn.f32x2 %0, %1, %2;" : "=l"(r) : "l"(a), "l"(b));
    return r;
}

// Packed epilogue for 2 columns of one row.
// |num|^2 = den*e, e = x2+p2-2xy (exact identity); dist = ln((den+s)/(den-s));
// out = -dist^2. Clamps provably inactive for these input ranges except the
// G>=0 guard (cancellation when x ~ p).
static __device__ __forceinline__ float2 epi2(uint64_t xy2, uint64_t x22,
                                              uint64_t p22, uint64_t one2,
                                              uint64_t n2, uint64_t m1_2) {
    const uint64_t m2   = fma2(x22, p22, one2);   // 1 + x2*p2
    const uint64_t den2 = fma2(xy2, n2, m2);      // den
    const uint64_t sp2  = add2(x22, p22);         // x2 + p2
    const uint64_t e2   = fma2(xy2, n2, sp2);     // |x-p|^2
    uint64_t G2 = mul2(den2, e2);
    float Gx, Gy;
    upk(G2, Gx, Gy);
    Gx = fmaxf(Gx, 1e-30f);
    Gy = fmaxf(Gy, 1e-30f);
    const float sx = Gx * rsqrtf(Gx);             // sqrt
    const float sy = Gy * rsqrtf(Gy);
    const uint64_t s2 = pk(sx, sy);
    const uint64_t u2 = add2(den2, s2);           // den + s
    const uint64_t v2 = fma2(s2, m1_2, den2);     // den - s
    float ux, uy, vx, vy;
    upk(u2, ux, uy);
    upk(v2, vx, vy);
    const float dx = __log2f(ux) - __log2f(vx);
    const float dy = __log2f(uy) - __log2f(vy);
    const float c = -0.4804530139182014f;         // -ln(2)^2
    return make_float2(dx * dx * c, dy * dy * c);
}

// ---------------------------------------------------------------------------
// grid = N/128 = 128 CTAs, 256 threads (8 warps). Warp w owns rows 16w..16w+15
// x ALL 128 prototype columns. A and B prep fully deduplicated. Packed f32x2
// epilogue. Single __syncthreads.
// ---------------------------------------------------------------------------
__global__ void __launch_bounds__(NTH)
geo_kernel(const float* __restrict__ x, const float* __restrict__ proto,
           float* __restrict__ out) {
    extern __shared__ char sm[];
    const uint32_t smb = smem_u32(sm);
    float* p2_s = (float*)(sm + SM_P2);

    const int tid  = threadIdx.x;
    const int wid  = tid >> 5;          // 0..7: row group
    const int lane = tid & 31;
    const int n0   = blockIdx.x * TM;

    // ---- issue ALL global loads first ----
    const int r0 = wid * 16 + (lane >> 2);
    const float* xr0 = x + (size_t)(n0 + r0) * D + 2 * (lane & 3);
    const float* xr1 = xr0 + 8 * D;

    float2 a00[4], a10[4], a01[4], a11[4];
    #pragma unroll
    for (int t = 0; t < 4; ++t) {
        a00[t] = *(const float2*)(xr0 + t * 16);        // (r0,   k=16t+c)
        a10[t] = *(const float2*)(xr1 + t * 16);        // (r0+8, k)
        a01[t] = *(const float2*)(xr0 + t * 16 + 8);    // (r0,   k+8)
        a11[t] = *(const float2*)(xr1 + t * 16 + 8);    // (r0+8, k+8)
    }
    const int br = tid >> 1;             // proto row 0..127
    const int bh = tid & 1;              // k-half
    const float4* p4 = (const float4*)(proto) + (size_t)br * 16 + bh * 8;
    float4 v[8];
    #pragma unroll
    for (int i = 0; i < 8; ++i) v[i] = p4[i];

    // ---- A: split + x^2 (covers proto-load latency) ----
    uint32_t ahi[16], alo[16];
    float s0 = 0.f, s1 = 0.f;
    #pragma unroll
    for (int t = 0; t < 4; ++t) {
        s0 += a00[t].x * a00[t].x + a00[t].y * a00[t].y +
              a01[t].x * a01[t].x + a01[t].y * a01[t].y;
        s1 += a10[t].x * a10[t].x + a10[t].y * a10[t].y +
              a11[t].x * a11[t].x + a11[t].y * a11[t].y;
        split2(a00[t].x, a00[t].y, ahi[4 * t + 0], alo[4 * t + 0]);
        split2(a10[t].x, a10[t].y, ahi[4 * t + 1], alo[4 * t + 1]);
        split2(a01[t].x, a01[t].y, ahi[4 * t + 2], alo[4 * t + 2]);
        split2(a11[t].x, a11[t].y, ahi[4 * t + 3], alo[4 * t + 3]);
    }
    s0 += __shfl_xor_sync(0xFFFFFFFFu, s0, 1);
    s0 += __shfl_xor_sync(0xFFFFFFFFu, s0, 2);
    s1 += __shfl_xor_sync(0xFFFFFFFFu, s1, 1);
    s1 += __shfl_xor_sync(0xFFFFFFFFu, s1, 2);
    const float x2a = s0, x2b = s1;

    // ---- B-prep: half-row per thread; norm via 1 shfl; 8 STS.128 ----
    {
        float s = 0.f;
        #pragma unroll
        for (int i = 0; i < 8; ++i)
            s += v[i].x * v[i].x + v[i].y * v[i].y + v[i].z * v[i].z + v[i].w * v[i].w;
        s += __shfl_xor_sync(0xFFFFFFFFu, s, 1);     // full row norm^2
        const float n  = fmaxf(sqrtf(s), 1e-15f);
        const float sc = fminf(1.0f, 0.999f / n);    // (1-BALL_EPS)/sqrt(c)
        if (bh == 0) p2_s[br] = s * sc * sc;

        uint32_t hi[16], lo[16];
        #pragma unroll
        for (int i = 0; i < 8; ++i) {
            split2(v[i].x * sc, v[i].y * sc, hi[2 * i],     lo[2 * i]);
            split2(v[i].z * sc, v[i].w * sc, hi[2 * i + 1], lo[2 * i + 1]);
        }
        // swizzle applied per 16B store (exact at 16B granularity)
        const uint32_t rbase = (uint32_t)br * ROWB + (uint32_t)bh * 64;
        #pragma unroll
        for (int j = 0; j < 4; ++j) {
            *(uint4*)(sm + SM_B + sw(rbase + j * 16)) =
                make_uint4(hi[4 * j], hi[4 * j + 1], hi[4 * j + 2], hi[4 * j + 3]);
            *(uint4*)(sm + SM_B + sw(rbase + 256 + j * 16)) =
                make_uint4(lo[4 * j], lo[4 * j + 1], lo[4 * j + 2], lo[4 * j + 3]);
        }
    }
    __syncthreads();

    // ---- MMA: 16 acc chains; chunk0 B frags feed both ahi and alo ----
    const int g     = lane >> 3;
    const int nOffB = ((g & 2) ? 8 : 0) + (lane & 7);
    const int kB    = (g & 1) * 8;

    float acc[16][4];
    #pragma unroll
    for (int j = 0; j < 16; ++j)
        #pragma unroll
        for (int u = 0; u < 4; ++u) acc[j][u] = 0.f;

    #pragma unroll
    for (int kgi = 0; kgi < 4; ++kgi) {               // chunk0: hi B
        const int kg = kgi * 16;
        #pragma unroll
        for (int nb = 0; nb < 8; ++nb) {
            const int nrow = nb * 16 + nOffB;
            uint32_t b[4];
            ldsm_x4(b, smb + SM_B + sw((uint32_t)nrow * ROWB + (uint32_t)(kg + kB) * 2));
            mma_bf16(acc[2 * nb],     &ahi[4 * kgi], b[0], b[1]);
            mma_bf16(acc[2 * nb + 1], &ahi[4 * kgi], b[2], b[3]);
            mma_bf16(acc[2 * nb],     &alo[4 * kgi], b[0], b[1]);
            mma_bf16(acc[2 * nb + 1], &alo[4 * kgi], b[2], b[3]);
        }
    }
    #pragma unroll
    for (int kgi = 0; kgi < 4; ++kgi) {               // chunk2: lo B, hi A
        const int kg = 128 + kgi * 16;
        #pragma unroll
        for (int nb = 0; nb < 8; ++nb) {
            const int nrow = nb * 16 + nOffB;
            uint32_t b[4];
            ldsm_x4(b, smb + SM_B + sw((uint32_t)nrow * ROWB + (uint32_t)(kg + kB) * 2));
            mma_bf16(acc[2 * nb],     &ahi[4 * kgi], b[0], b[1]);
            mma_bf16(acc[2 * nb + 1], &ahi[4 * kgi], b[2], b[3]);
        }
    }

    // ---- packed epilogue straight from accumulators ----
    {
        const uint64_t one2 = pk(1.0f, 1.0f);
        const uint64_t n2   = pk(-2.0f, -2.0f);
        const uint64_t m1_2 = pk(-1.0f, -1.0f);
        const uint64_t x2a2 = pk(x2a, x2a);
        const uint64_t x2b2 = pk(x2b, x2b);
        float* orowa = out + (size_t)(n0 + r0) * KP;
        float* orowb = orowa + 8 * KP;

        #pragma unroll
        for (int j = 0; j < 16; ++j) {
            const int c = j * 8 + 2 * (lane & 3);
            const float2 p2f = *(const float2*)&p2_s[c];
            const uint64_t p22 = pk(p2f.x, p2f.y);
            const uint64_t xya = pk(acc[j][0], acc[j][1]);
            const uint64_t xyb = pk(acc[j][2], acc[j][3]);
            *(float2*)(orowa + c) = epi2(xya, x2a2, p22, one2, n2, m1_2);
            *(float2*)(orowb + c) = epi2(xyb, x2b2, p22, one2, n2, m1_2);
        }
    }
}

// ---------------------------------------------------------------------------
extern "C" void kernel_launch(void* const* d_in, const int* in_sizes, int n_in,
                              void* d_out, int out_size) {
    const float* x;
    const float* proto;
    int xs;
    if (in_sizes[0] == KP * D) {
        proto = (const float*)d_in[0];
        x     = (const float*)d_in[1];
        xs    = in_sizes[1];
    } else {
        x     = (const float*)d_in[0];
        proto = (const float*)d_in[1];
        xs    = in_sizes[0];
    }
    const int N = xs / D;  // 16384
    float* out = (float*)d_out;

    cudaFuncSetAttribute(geo_kernel, cudaFuncAttributeMaxDynamicSharedMemorySize, SM_DYN);
    geo_kernel<<<N / TM, NTH, SM_DYN>>>(x, proto, out);
}

// round 16
// speedup vs baseline: 1.1860x; 1.1860x over previous
#include <cuda_runtime.h>
#include <cuda_bf16.h>
#include <math.h>
#include <stdint.h>

#define D     64
#define TM    128       // x rows per CTA
#define KP    128       // all prototypes in every CTA
#define NTH   256
#define ROWB  384       // bytes per B row; chunk0=hi @0, chunk2=lo @+256

// smem layout
#define SM_B    0                      // 128 x 384B = 49152
#define SM_P2   49152                  // 128 floats: p^2
#define SM_LBB  (SM_P2 + 512)          // 128 floats: lg2(1 - p^2)
#define SM_DYN  (SM_LBB + 512)         // 50176 B

static __device__ __forceinline__ uint32_t sw(uint32_t off) {
    return off ^ ((off >> 3) & 0x70);
}

static __device__ __forceinline__ uint32_t smem_u32(const void* p) {
    uint32_t a;
    asm("{ .reg .u64 t; cvta.to.shared.u64 t, %1; cvt.u32.u64 %0, t; }" : "=r"(a) : "l"(p));
    return a;
}

static __device__ __forceinline__ void ldsm_x4(uint32_t* r, uint32_t addr) {
    asm volatile("ldmatrix.sync.aligned.m8n8.x4.shared.b16 {%0,%1,%2,%3}, [%4];"
                 : "=r"(r[0]), "=r"(r[1]), "=r"(r[2]), "=r"(r[3]) : "r"(addr));
}

static __device__ __forceinline__ void mma_bf16(float* c, const uint32_t* a,
                                                uint32_t b0, uint32_t b1) {
    asm volatile(
        "mma.sync.aligned.m16n8k16.row.col.f32.bf16.bf16.f32 "
        "{%0,%1,%2,%3}, {%4,%5,%6,%7}, {%8,%9}, {%0,%1,%2,%3};"
        : "+f"(c[0]), "+f"(c[1]), "+f"(c[2]), "+f"(c[3])
        : "r"(a[0]), "r"(a[1]), "r"(a[2]), "r"(a[3]), "r"(b0), "r"(b1));
}

static __device__ __forceinline__ void split2(float v0, float v1,
                                              uint32_t& hi, uint32_t& lo) {
    __nv_bfloat162 h = __floats2bfloat162_rn(v0, v1);
    float r0 = v0 - __bfloat162float(__low2bfloat16(h));
    float r1 = v1 - __bfloat162float(__high2bfloat16(h));
    __nv_bfloat162 l = __floats2bfloat162_rn(r0, r1);
    hi = *reinterpret_cast<uint32_t*>(&h);
    lo = *reinterpret_cast<uint32_t*>(&l);
}

// ---- packed f32x2 helpers (sm_100-family PTX) ----
static __device__ __forceinline__ uint64_t pk(float a, float b) {
    uint64_t r;
    asm("mov.b64 %0, {%1, %2};" : "=l"(r) : "f"(a), "f"(b));
    return r;
}
static __device__ __forceinline__ void upk(uint64_t v, float& a, float& b) {
    asm("mov.b64 {%0, %1}, %2;" : "=f"(a), "=f"(b) : "l"(v));
}
static __device__ __forceinline__ uint64_t fma2(uint64_t a, uint64_t b, uint64_t c) {
    uint64_t r;
    asm("fma.rn.f32x2 %0, %1, %2, %3;" : "=l"(r) : "l"(a), "l"(b), "l"(c));
    return r;
}
static __device__ __forceinline__ uint64_t add2(uint64_t a, uint64_t b) {
    uint64_t r;
    asm("add.rn.f32x2 %0, %1, %2;" : "=l"(r) : "l"(a), "l"(b));
    return r;
}
static __device__ __forceinline__ uint64_t mul2(uint64_t a, uint64_t b) {
    uint64_t r;
    asm("mul.rn.f32x2 %0, %1, %2;" : "=l"(r) : "l"(a), "l"(b));
    return r;
}

// 2-MUFU epilogue for 2 columns of one row.
// Exact identities: |num|^2 = den*e (e = x2+p2-2xy = |x-p|^2);
//   (den+s)^2 = den*(den+e+2s);  den - e = (1-x2)(1-p2) = bb
// => dist = ln((den+e+2s)/bb) with lg2(bb) precomputed per row+col.
// Input ranges: den in [0.37,1.75], z <= 0.91 -> ref clamps never bind.
static __device__ __forceinline__ float2 epi2(uint64_t xy2, uint64_t x22,
                                              uint64_t p22, uint64_t lbb2,
                                              uint64_t one2, uint64_t n2,
                                              uint64_t two2) {
    const uint64_t m2   = fma2(x22, p22, one2);   // 1 + x2*p2
    const uint64_t den2 = fma2(xy2, n2, m2);      // den
    const uint64_t sp2  = add2(x22, p22);         // x2 + p2
    const uint64_t e2   = fma2(xy2, n2, sp2);     // |x-p|^2
    const uint64_t G2   = mul2(den2, e2);         // |num|^2
    float Gx, Gy;
    upk(G2, Gx, Gy);
    Gx = fmaxf(Gx, 1e-30f);                       // guard tiny-negative (x ~ p)
    Gy = fmaxf(Gy, 1e-30f);
    const uint64_t s2 = pk(Gx * rsqrtf(Gx), Gy * rsqrtf(Gy));   // sqrt
    uint64_t w2 = add2(den2, e2);
    w2 = fma2(s2, two2, w2);                      // den + e + 2s
    float wx, wy, lx, ly;
    upk(w2, wx, wy);
    upk(lbb2, lx, ly);
    const float tx = __log2f(wx) - lx;            // dist / ln2
    const float ty = __log2f(wy) - ly;
    const float cc = -0.4804530139182014f;        // -(ln2)^2
    return make_float2(tx * tx * cc, ty * ty * cc);
}

// ---------------------------------------------------------------------------
// grid = N/128 = 128 CTAs, 256 threads (8 warps). Warp w owns rows 16w..16w+15
// x ALL 128 prototype columns. A and B prep fully deduplicated. Packed f32x2 +
// 2-MUFU epilogue. Single __syncthreads.
// ---------------------------------------------------------------------------
__global__ void __launch_bounds__(NTH)
geo_kernel(const float* __restrict__ x, const float* __restrict__ proto,
           float* __restrict__ out) {
    extern __shared__ char sm[];
    const uint32_t smb = smem_u32(sm);
    float* p2_s  = (float*)(sm + SM_P2);
    float* lbb_s = (float*)(sm + SM_LBB);

    const int tid  = threadIdx.x;
    const int wid  = tid >> 5;          // 0..7: row group
    const int lane = tid & 31;
    const int n0   = blockIdx.x * TM;

    // ---- issue ALL global loads first ----
    const int r0 = wid * 16 + (lane >> 2);
    const float* xr0 = x + (size_t)(n0 + r0) * D + 2 * (lane & 3);
    const float* xr1 = xr0 + 8 * D;

    float2 a00[4], a10[4], a01[4], a11[4];
    #pragma unroll
    for (int t = 0; t < 4; ++t) {
        a00[t] = *(const float2*)(xr0 + t * 16);        // (r0,   k=16t+c)
        a10[t] = *(const float2*)(xr1 + t * 16);        // (r0+8, k)
        a01[t] = *(const float2*)(xr0 + t * 16 + 8);    // (r0,   k+8)
        a11[t] = *(const float2*)(xr1 + t * 16 + 8);    // (r0+8, k+8)
    }
    const int br = tid >> 1;             // proto row 0..127
    const int bh = tid & 1;              // k-half
    const float4* p4 = (const float4*)(proto) + (size_t)br * 16 + bh * 8;
    float4 v[8];
    #pragma unroll
    for (int i = 0; i < 8; ++i) v[i] = p4[i];

    // ---- A: split + x^2 (covers proto-load latency) ----
    uint32_t ahi[16], alo[16];
    float s0 = 0.f, s1 = 0.f;
    #pragma unroll
    for (int t = 0; t < 4; ++t) {
        s0 += a00[t].x * a00[t].x + a00[t].y * a00[t].y +
              a01[t].x * a01[t].x + a01[t].y * a01[t].y;
        s1 += a10[t].x * a10[t].x + a10[t].y * a10[t].y +
              a11[t].x * a11[t].x + a11[t].y * a11[t].y;
        split2(a00[t].x, a00[t].y, ahi[4 * t + 0], alo[4 * t + 0]);
        split2(a10[t].x, a10[t].y, ahi[4 * t + 1], alo[4 * t + 1]);
        split2(a01[t].x, a01[t].y, ahi[4 * t + 2], alo[4 * t + 2]);
        split2(a11[t].x, a11[t].y, ahi[4 * t + 3], alo[4 * t + 3]);
    }
    s0 += __shfl_xor_sync(0xFFFFFFFFu, s0, 1);
    s0 += __shfl_xor_sync(0xFFFFFFFFu, s0, 2);
    s1 += __shfl_xor_sync(0xFFFFFFFFu, s1, 1);
    s1 += __shfl_xor_sync(0xFFFFFFFFu, s1, 2);
    const float x2a = s0, x2b = s1;

    // ---- B-prep: half-row per thread; norm via 1 shfl; 8 STS.128 ----
    {
        float s = 0.f;
        #pragma unroll
        for (int i = 0; i < 8; ++i)
            s += v[i].x * v[i].x + v[i].y * v[i].y + v[i].z * v[i].z + v[i].w * v[i].w;
        s += __shfl_xor_sync(0xFFFFFFFFu, s, 1);     // full row norm^2
        const float n  = fmaxf(sqrtf(s), 1e-15f);
        const float sc = fminf(1.0f, 0.999f / n);    // (1-BALL_EPS)/sqrt(c)
        if (bh == 0) {
            const float p2v = s * sc * sc;
            p2_s[br]  = p2v;
            lbb_s[br] = __log2f(1.0f - p2v);
        }

        uint32_t hi[16], lo[16];
        #pragma unroll
        for (int i = 0; i < 8; ++i) {
            split2(v[i].x * sc, v[i].y * sc, hi[2 * i],     lo[2 * i]);
            split2(v[i].z * sc, v[i].w * sc, hi[2 * i + 1], lo[2 * i + 1]);
        }
        // swizzle applied per 16B store (exact at 16B granularity)
        const uint32_t rbase = (uint32_t)br * ROWB + (uint32_t)bh * 64;
        #pragma unroll
        for (int j = 0; j < 4; ++j) {
            *(uint4*)(sm + SM_B + sw(rbase + j * 16)) =
                make_uint4(hi[4 * j], hi[4 * j + 1], hi[4 * j + 2], hi[4 * j + 3]);
            *(uint4*)(sm + SM_B + sw(rbase + 256 + j * 16)) =
                make_uint4(lo[4 * j], lo[4 * j + 1], lo[4 * j + 2], lo[4 * j + 3]);
        }
    }
    __syncthreads();

    // ---- MMA: 16 acc chains; chunk0 B frags feed both ahi and alo ----
    const int g     = lane >> 3;
    const int nOffB = ((g & 2) ? 8 : 0) + (lane & 7);
    const int kB    = (g & 1) * 8;

    float acc[16][4];
    #pragma unroll
    for (int j = 0; j < 16; ++j)
        #pragma unroll
        for (int u = 0; u < 4; ++u) acc[j][u] = 0.f;

    #pragma unroll
    for (int kgi = 0; kgi < 4; ++kgi) {               // chunk0: hi B
        const int kg = kgi * 16;
        #pragma unroll
        for (int nb = 0; nb < 8; ++nb) {
            const int nrow = nb * 16 + nOffB;
            uint32_t b[4];
            ldsm_x4(b, smb + SM_B + sw((uint32_t)nrow * ROWB + (uint32_t)(kg + kB) * 2));
            mma_bf16(acc[2 * nb],     &ahi[4 * kgi], b[0], b[1]);
            mma_bf16(acc[2 * nb + 1], &ahi[4 * kgi], b[2], b[3]);
            mma_bf16(acc[2 * nb],     &alo[4 * kgi], b[0], b[1]);
            mma_bf16(acc[2 * nb + 1], &alo[4 * kgi], b[2], b[3]);
        }
    }
    #pragma unroll
    for (int kgi = 0; kgi < 4; ++kgi) {               // chunk2: lo B, hi A
        const int kg = 128 + kgi * 16;
        #pragma unroll
        for (int nb = 0; nb < 8; ++nb) {
            const int nrow = nb * 16 + nOffB;
            uint32_t b[4];
            ldsm_x4(b, smb + SM_B + sw((uint32_t)nrow * ROWB + (uint32_t)(kg + kB) * 2));
            mma_bf16(acc[2 * nb],     &ahi[4 * kgi], b[0], b[1]);
            mma_bf16(acc[2 * nb + 1], &ahi[4 * kgi], b[2], b[3]);
        }
    }

    // ---- packed 2-MUFU epilogue straight from accumulators ----
    {
        const uint64_t one2 = pk(1.0f, 1.0f);
        const uint64_t n2   = pk(-2.0f, -2.0f);
        const uint64_t two2 = pk(2.0f, 2.0f);
        const uint64_t x2a2 = pk(x2a, x2a);
        const uint64_t x2b2 = pk(x2b, x2b);
        const float l2a = __log2f(1.0f - x2a);
        const float l2b = __log2f(1.0f - x2b);
        const uint64_t l2a2 = pk(l2a, l2a);
        const uint64_t l2b2 = pk(l2b, l2b);
        float* orowa = out + (size_t)(n0 + r0) * KP;
        float* orowb = orowa + 8 * KP;

        #pragma unroll
        for (int j = 0; j < 16; ++j) {
            const int c = j * 8 + 2 * (lane & 3);
            const float2 p2f = *(const float2*)&p2_s[c];
            const float2 lbf = *(const float2*)&lbb_s[c];
            const uint64_t p22 = pk(p2f.x, p2f.y);
            const uint64_t lb2 = pk(lbf.x, lbf.y);
            const uint64_t lbba = add2(l2a2, lb2);   // lg2(bb) row a
            const uint64_t lbbb = add2(l2b2, lb2);   // lg2(bb) row b
            const uint64_t xya = pk(acc[j][0], acc[j][1]);
            const uint64_t xyb = pk(acc[j][2], acc[j][3]);
            *(float2*)(orowa + c) = epi2(xya, x2a2, p22, lbba, one2, n2, two2);
            *(float2*)(orowb + c) = epi2(xyb, x2b2, p22, lbbb, one2, n2, two2);
        }
    }
}

// ---------------------------------------------------------------------------
extern "C" void kernel_launch(void* const* d_in, const int* in_sizes, int n_in,
                              void* d_out, int out_size) {
    const float* x;
    const float* proto;
    int xs;
    if (in_sizes[0] == KP * D) {
        proto = (const float*)d_in[0];
        x     = (const float*)d_in[1];
        xs    = in_sizes[1];
    } else {
        x     = (const float*)d_in[0];
        proto = (const float*)d_in[1];
        xs    = in_sizes[0];
    }
    const int N = xs / D;  // 16384
    float* out = (float*)d_out;

    cudaFuncSetAttribute(geo_kernel, cudaFuncAttributeMaxDynamicSharedMemorySize, SM_DYN);
    geo_kernel<<<N / TM, NTH, SM_DYN>>>(x, proto, out);
}

// round 17
// speedup vs baseline: 1.2179x; 1.0269x over previous
#include <cuda_runtime.h>
#include <cuda_bf16.h>
#include <math.h>
#include <stdint.h>

#define D     64
#define TM    128       // x rows per CTA
#define KP    128       // all prototypes in every CTA
#define NTH   256
#define ROWB  384       // bytes per B row; chunk0=hi @0, chunk2=lo @+256

// smem layout
#define SM_B    0                      // 128 x 384B = 49152
#define SM_P2   49152                  // 128 floats: p^2
#define SM_LBB  (SM_P2 + 512)          // 128 floats: lg2(1 - p^2)
#define SM_DYN  (SM_LBB + 512)         // 50176 B

static __device__ __forceinline__ uint32_t sw(uint32_t off) {
    return off ^ ((off >> 3) & 0x70);
}

static __device__ __forceinline__ uint32_t smem_u32(const void* p) {
    uint32_t a;
    asm("{ .reg .u64 t; cvta.to.shared.u64 t, %1; cvt.u32.u64 %0, t; }" : "=r"(a) : "l"(p));
    return a;
}

static __device__ __forceinline__ void ldsm_x4(uint32_t* r, uint32_t addr) {
    asm volatile("ldmatrix.sync.aligned.m8n8.x4.shared.b16 {%0,%1,%2,%3}, [%4];"
                 : "=r"(r[0]), "=r"(r[1]), "=r"(r[2]), "=r"(r[3]) : "r"(addr));
}

static __device__ __forceinline__ void mma_bf16(float* c, const uint32_t* a,
                                                uint32_t b0, uint32_t b1) {
    asm volatile(
        "mma.sync.aligned.m16n8k16.row.col.f32.bf16.bf16.f32 "
        "{%0,%1,%2,%3}, {%4,%5,%6,%7}, {%8,%9}, {%0,%1,%2,%3};"
        : "+f"(c[0]), "+f"(c[1]), "+f"(c[2]), "+f"(c[3])
        : "r"(a[0]), "r"(a[1]), "r"(a[2]), "r"(a[3]), "r"(b0), "r"(b1));
}

static __device__ __forceinline__ void split2(float v0, float v1,
                                              uint32_t& hi, uint32_t& lo) {
    __nv_bfloat162 h = __floats2bfloat162_rn(v0, v1);
    float r0 = v0 - __bfloat162float(__low2bfloat16(h));
    float r1 = v1 - __bfloat162float(__high2bfloat16(h));
    __nv_bfloat162 l = __floats2bfloat162_rn(r0, r1);
    hi = *reinterpret_cast<uint32_t*>(&h);
    lo = *reinterpret_cast<uint32_t*>(&l);
}

// ---- packed f32x2 helpers (sm_100-family PTX) ----
static __device__ __forceinline__ uint64_t pk(float a, float b) {
    uint64_t r;
    asm("mov.b64 %0, {%1, %2};" : "=l"(r) : "f"(a), "f"(b));
    return r;
}
static __device__ __forceinline__ void upk(uint64_t v, float& a, float& b) {
    asm("mov.b64 {%0, %1}, %2;" : "=f"(a), "=f"(b) : "l"(v));
}
static __device__ __forceinline__ uint64_t fma2(uint64_t a, uint64_t b, uint64_t c) {
    uint64_t r;
    asm("fma.rn.f32x2 %0, %1, %2, %3;" : "=l"(r) : "l"(a), "l"(b), "l"(c));
    return r;
}
static __device__ __forceinline__ uint64_t add2(uint64_t a, uint64_t b) {
    uint64_t r;
    asm("add.rn.f32x2 %0, %1, %2;" : "=l"(r) : "l"(a), "l"(b));
    return r;
}
static __device__ __forceinline__ uint64_t mul2(uint64_t a, uint64_t b) {
    uint64_t r;
    asm("mul.rn.f32x2 %0, %1, %2;" : "=l"(r) : "l"(a), "l"(b));
    return r;
}
static __device__ __forceinline__ float sqrt_ap(float a) {
    float r;
    asm("sqrt.approx.f32 %0, %1;" : "=f"(r) : "f"(a));
    return r;
}

// 2-MUFU epilogue for 2 columns of one row.
// Exact identities: |num|^2 = den*e (e = x2+p2-2xy = |x-p|^2);
//   (den+s)^2 = den*(den+e+2s);  den - e = (1-x2)(1-p2) = bb
// => dist = ln((den+e+2s)/bb), lg2(bb) precomputed per row+col.
// |G| guard: G<0 only via rounding when x ~ p; |G| -> s ~ 0 -> dist ~ 0 (correct limit).
static __device__ __forceinline__ float2 epi2(uint64_t xy2, uint64_t x22,
                                              uint64_t p22, uint64_t lbb2,
                                              uint64_t one2, uint64_t n2,
                                              uint64_t two2) {
    const uint64_t m2   = fma2(x22, p22, one2);   // 1 + x2*p2
    const uint64_t den2 = fma2(xy2, n2, m2);      // den
    const uint64_t sp2  = add2(x22, p22);         // x2 + p2
    const uint64_t e2   = fma2(xy2, n2, sp2);     // |x-p|^2
    const uint64_t G2   = mul2(den2, e2);         // |num|^2
    float Gx, Gy;
    upk(G2, Gx, Gy);
    const uint64_t s2 = pk(sqrt_ap(fabsf(Gx)), sqrt_ap(fabsf(Gy)));
    uint64_t w2 = add2(den2, e2);
    w2 = fma2(s2, two2, w2);                      // den + e + 2s
    float wx, wy, lx, ly;
    upk(w2, wx, wy);
    upk(lbb2, lx, ly);
    const float tx = __log2f(wx) - lx;            // dist / ln2
    const float ty = __log2f(wy) - ly;
    const float cc = -0.4804530139182014f;        // -(ln2)^2
    return make_float2(tx * tx * cc, ty * ty * cc);
}

// ---------------------------------------------------------------------------
// grid = N/128 = 128 CTAs, 256 threads (8 warps). Warp w owns rows 16w..16w+15
// x ALL 128 prototype columns, processed in TWO 64-column passes (acc live set
// halved -> scheduling headroom; epilogue interleaves with second MMA pass
// across warps). A and B prep fully deduplicated. Single __syncthreads.
// ---------------------------------------------------------------------------
__global__ void __launch_bounds__(NTH)
geo_kernel(const float* __restrict__ x, const float* __restrict__ proto,
           float* __restrict__ out) {
    extern __shared__ char sm[];
    const uint32_t smb = smem_u32(sm);
    float* p2_s  = (float*)(sm + SM_P2);
    float* lbb_s = (float*)(sm + SM_LBB);

    const int tid  = threadIdx.x;
    const int wid  = tid >> 5;          // 0..7: row group
    const int lane = tid & 31;
    const int n0   = blockIdx.x * TM;

    // ---- issue ALL global loads first ----
    const int r0 = wid * 16 + (lane >> 2);
    const float* xr0 = x + (size_t)(n0 + r0) * D + 2 * (lane & 3);
    const float* xr1 = xr0 + 8 * D;

    float2 a00[4], a10[4], a01[4], a11[4];
    #pragma unroll
    for (int t = 0; t < 4; ++t) {
        a00[t] = *(const float2*)(xr0 + t * 16);        // (r0,   k=16t+c)
        a10[t] = *(const float2*)(xr1 + t * 16);        // (r0+8, k)
        a01[t] = *(const float2*)(xr0 + t * 16 + 8);    // (r0,   k+8)
        a11[t] = *(const float2*)(xr1 + t * 16 + 8);    // (r0+8, k+8)
    }
    const int br = tid >> 1;             // proto row 0..127
    const int bh = tid & 1;              // k-half
    const float4* p4 = (const float4*)(proto) + (size_t)br * 16 + bh * 8;
    float4 v[8];
    #pragma unroll
    for (int i = 0; i < 8; ++i) v[i] = p4[i];

    // ---- A: split + x^2 (covers proto-load latency) ----
    uint32_t ahi[16], alo[16];
    float s0 = 0.f, s1 = 0.f;
    #pragma unroll
    for (int t = 0; t < 4; ++t) {
        s0 += a00[t].x * a00[t].x + a00[t].y * a00[t].y +
              a01[t].x * a01[t].x + a01[t].y * a01[t].y;
        s1 += a10[t].x * a10[t].x + a10[t].y * a10[t].y +
              a11[t].x * a11[t].x + a11[t].y * a11[t].y;
        split2(a00[t].x, a00[t].y, ahi[4 * t + 0], alo[4 * t + 0]);
        split2(a10[t].x, a10[t].y, ahi[4 * t + 1], alo[4 * t + 1]);
        split2(a01[t].x, a01[t].y, ahi[4 * t + 2], alo[4 * t + 2]);
        split2(a11[t].x, a11[t].y, ahi[4 * t + 3], alo[4 * t + 3]);
    }
    s0 += __shfl_xor_sync(0xFFFFFFFFu, s0, 1);
    s0 += __shfl_xor_sync(0xFFFFFFFFu, s0, 2);
    s1 += __shfl_xor_sync(0xFFFFFFFFu, s1, 1);
    s1 += __shfl_xor_sync(0xFFFFFFFFu, s1, 2);
    const float x2a = s0, x2b = s1;

    // ---- B-prep: half-row per thread; norm via 1 shfl; 8 STS.128 ----
    {
        float s = 0.f;
        #pragma unroll
        for (int i = 0; i < 8; ++i)
            s += v[i].x * v[i].x + v[i].y * v[i].y + v[i].z * v[i].z + v[i].w * v[i].w;
        s += __shfl_xor_sync(0xFFFFFFFFu, s, 1);     // full row norm^2
        const float n  = fmaxf(sqrtf(s), 1e-15f);
        const float sc = fminf(1.0f, 0.999f / n);    // (1-BALL_EPS)/sqrt(c)
        if (bh == 0) {
            const float p2v = s * sc * sc;
            p2_s[br]  = p2v;
            lbb_s[br] = __log2f(1.0f - p2v);
        }

        uint32_t hi[16], lo[16];
        #pragma unroll
        for (int i = 0; i < 8; ++i) {
            split2(v[i].x * sc, v[i].y * sc, hi[2 * i],     lo[2 * i]);
            split2(v[i].z * sc, v[i].w * sc, hi[2 * i + 1], lo[2 * i + 1]);
        }
        // swizzle applied per 16B store (exact at 16B granularity)
        const uint32_t rbase = (uint32_t)br * ROWB + (uint32_t)bh * 64;
        #pragma unroll
        for (int j = 0; j < 4; ++j) {
            *(uint4*)(sm + SM_B + sw(rbase + j * 16)) =
                make_uint4(hi[4 * j], hi[4 * j + 1], hi[4 * j + 2], hi[4 * j + 3]);
            *(uint4*)(sm + SM_B + sw(rbase + 256 + j * 16)) =
                make_uint4(lo[4 * j], lo[4 * j + 1], lo[4 * j + 2], lo[4 * j + 3]);
        }
    }
    __syncthreads();

    // ---- MMA + epilogue in two 64-column passes ----
    const int g     = lane >> 3;
    const int nOffB = ((g & 2) ? 8 : 0) + (lane & 7);
    const int kB    = (g & 1) * 8;

    const uint64_t one2 = pk(1.0f, 1.0f);
    const uint64_t n2   = pk(-2.0f, -2.0f);
    const uint64_t two2 = pk(2.0f, 2.0f);
    const uint64_t x2a2 = pk(x2a, x2a);
    const uint64_t x2b2 = pk(x2b, x2b);
    const float l2a = __log2f(1.0f - x2a);
    const float l2b = __log2f(1.0f - x2b);
    const uint64_t l2a2 = pk(l2a, l2a);
    const uint64_t l2b2 = pk(l2b, l2b);
    float* orowa = out + (size_t)(n0 + r0) * KP;
    float* orowb = orowa + 8 * KP;

    #pragma unroll
    for (int half = 0; half < 2; ++half) {
        const int c0 = half * 64;

        float acc[8][4];
        #pragma unroll
        for (int j = 0; j < 8; ++j)
            #pragma unroll
            for (int u = 0; u < 4; ++u) acc[j][u] = 0.f;

        #pragma unroll
        for (int kgi = 0; kgi < 4; ++kgi) {               // chunk0: hi B
            const int kg = kgi * 16;
            #pragma unroll
            for (int nb = 0; nb < 4; ++nb) {
                const int nrow = c0 + nb * 16 + nOffB;
                uint32_t b[4];
                ldsm_x4(b, smb + SM_B + sw((uint32_t)nrow * ROWB + (uint32_t)(kg + kB) * 2));
                mma_bf16(acc[2 * nb],     &ahi[4 * kgi], b[0], b[1]);
                mma_bf16(acc[2 * nb + 1], &ahi[4 * kgi], b[2], b[3]);
                mma_bf16(acc[2 * nb],     &alo[4 * kgi], b[0], b[1]);
                mma_bf16(acc[2 * nb + 1], &alo[4 * kgi], b[2], b[3]);
            }
        }
        #pragma unroll
        for (int kgi = 0; kgi < 4; ++kgi) {               // chunk2: lo B, hi A
            const int kg = 128 + kgi * 16;
            #pragma unroll
            for (int nb = 0; nb < 4; ++nb) {
                const int nrow = c0 + nb * 16 + nOffB;
                uint32_t b[4];
                ldsm_x4(b, smb + SM_B + sw((uint32_t)nrow * ROWB + (uint32_t)(kg + kB) * 2));
                mma_bf16(acc[2 * nb],     &ahi[4 * kgi], b[0], b[1]);
                mma_bf16(acc[2 * nb + 1], &ahi[4 * kgi], b[2], b[3]);
            }
        }

        // ---- packed 2-MUFU epilogue for this column half ----
        #pragma unroll
        for (int j = 0; j < 8; ++j) {
            const int c = c0 + j * 8 + 2 * (lane & 3);
            const float2 p2f = *(const float2*)&p2_s[c];
            const float2 lbf = *(const float2*)&lbb_s[c];
            const uint64_t p22 = pk(p2f.x, p2f.y);
            const uint64_t lb2 = pk(lbf.x, lbf.y);
            const uint64_t lbba = add2(l2a2, lb2);   // lg2(bb) row a
            const uint64_t lbbb = add2(l2b2, lb2);   // lg2(bb) row b
            const uint64_t xya = pk(acc[j][0], acc[j][1]);
            const uint64_t xyb = pk(acc[j][2], acc[j][3]);
            *(float2*)(orowa + c) = epi2(xya, x2a2, p22, lbba, one2, n2, two2);
            *(float2*)(orowb + c) = epi2(xyb, x2b2, p22, lbbb, one2, n2, two2);
        }
    }
}

// ---------------------------------------------------------------------------
extern "C" void kernel_launch(void* const* d_in, const int* in_sizes, int n_in,
                              void* d_out, int out_size) {
    const float* x;
    const float* proto;
    int xs;
    if (in_sizes[0] == KP * D) {
        proto = (const float*)d_in[0];
        x     = (const float*)d_in[1];
        xs    = in_sizes[1];
    } else {
        x     = (const float*)d_in[0];
        proto = (const float*)d_in[1];
        xs    = in_sizes[0];
    }
    const int N = xs / D;  // 16384
    float* out = (float*)d_out;

    cudaFuncSetAttribute(geo_kernel, cudaFuncAttributeMaxDynamicSharedMemorySize, SM_DYN);
    geo_kernel<<<N / TM, NTH, SM_DYN>>>(x, proto, out);
}